// round 12
// baseline (speedup 1.0000x reference)
#include <cuda_runtime.h>
#include <cuda_bf16.h>
#include <math.h>

#define H 128
#define MAXM 2048
#define MAXJ 8192
#define MAIN_BLOCKS 444
#define MAIN_THREADS 256
#define WROWS 16                   // rows per warp
#define TILE (8 * WROWS)           // 128 ops per block-iteration
#define SAW 68                     // h0 smem row stride in 32-bit words
#define PREROWS 16

// -------- device scratch --------
__device__ float d_g[H];
__device__ float d_A[MAXM * H];
__device__ float d_B[MAXJ * H];
__device__ unsigned long long d_maxkey;
__device__ unsigned int d_ticket;
__device__ float d_blkM[MAIN_BLOCKS];
__device__ float d_blkE[MAIN_BLOCKS];
__device__ float d_blkS[MAIN_BLOCKS];

__device__ __forceinline__ unsigned int fkey(float f) {
    unsigned int b = __float_as_uint(f);
    return (b & 0x80000000u) ? ~b : (b | 0x80000000u);
}

__device__ __forceinline__ unsigned int bf2(float lo, float hi) {
    __nv_bfloat162 v = __float22bfloat162_rn(make_float2(lo, hi));
    return *(unsigned int*)&v;
}

__device__ __forceinline__ void mma_bf16(float c[4], const unsigned a[4],
                                         unsigned b0, unsigned b1) {
    asm volatile(
        "mma.sync.aligned.m16n8k16.row.col.f32.bf16.bf16.f32 "
        "{%0,%1,%2,%3}, {%4,%5,%6,%7}, {%8,%9}, {%0,%1,%2,%3};"
        : "+f"(c[0]), "+f"(c[1]), "+f"(c[2]), "+f"(c[3])
        : "r"(a[0]), "r"(a[1]), "r"(a[2]), "r"(a[3]), "r"(b0), "r"(b1));
}

__device__ __forceinline__ void osm_merge(float& m, float& se, float& ss,
                                          float m2, float se2, float ss2) {
    float M = fmaxf(m, se2 > 0.f ? m2 : m);
    if (m2 > M) M = m2;
    float a1 = (se > 0.f) ? expf(m - M) : 0.f;
    float a2 = (se2 > 0.f) ? expf(m2 - M) : 0.f;
    se = se * a1 + se2 * a2;
    ss = ss * a1 + ss2 * a2;
    m = M;
}

// ---------------- precompute: g, A = x_m@W0[2H:3H], B = x_job@W0[3H:4H] ----------------
__global__ void k_pre(const float* __restrict__ xg,
                      const float* __restrict__ xm,
                      const float* __restrict__ xj,
                      const float* __restrict__ W0,
                      const float* __restrict__ b0,
                      int M, int J) {
    const int t = threadIdx.x;
    if ((int)blockIdx.x == (int)gridDim.x - 1) {
        __shared__ float s[2 * H];
        if (t == 0) { d_maxkey = 0ull; d_ticket = 0u; }
        s[t] = xg[t];
        s[t + H] = xg[t + H];
        __syncthreads();
        float acc = b0[t];
        for (int k0 = 0; k0 < 2 * H; k0 += 8) {
            float wv[8];
#pragma unroll
            for (int u = 0; u < 8; u++) wv[u] = W0[(k0 + u) * H + t];
#pragma unroll
            for (int u = 0; u < 8; u++) acc += s[k0 + u] * wv[u];
        }
        d_g[t] = acc;
        return;
    }
    const int blocksA = (M + PREROWS - 1) / PREROWS;
    __shared__ float s[PREROWS][H];
    const float* src; float* dst;
    int row0, nrows, off;
    if ((int)blockIdx.x < blocksA) {
        row0 = blockIdx.x * PREROWS; nrows = min(PREROWS, M - row0);
        src = xm; off = 2 * H; dst = d_A;
    } else {
        row0 = ((int)blockIdx.x - blocksA) * PREROWS; nrows = min(PREROWS, J - row0);
        src = xj; off = 3 * H; dst = d_B;
    }
#pragma unroll
    for (int r = 0; r < PREROWS; r++)
        s[r][t] = (r < nrows) ? src[(row0 + r) * H + t] : 0.f;
    __syncthreads();
    float acc[PREROWS];
#pragma unroll
    for (int r = 0; r < PREROWS; r++) acc[r] = 0.f;
    const float* Wp = W0 + off * H + t;
#pragma unroll 1
    for (int k0 = 0; k0 < H; k0 += 8) {
        float wv[8];
#pragma unroll
        for (int u = 0; u < 8; u++) wv[u] = Wp[(k0 + u) * H];
#pragma unroll
        for (int u = 0; u < 8; u++) {
#pragma unroll
            for (int r = 0; r < PREROWS; r++) acc[r] += s[r][k0 + u] * wv[u];
        }
    }
    for (int r = 0; r < nrows; r++) dst[(row0 + r) * H + t] = acc[r];
}

// ---------------- main: gather + bf16 MMA layer1 (2-pass n-split) + fused layer2 + softmax --------
__global__ void __launch_bounds__(MAIN_THREADS, 3)
k_main(const int* __restrict__ m_ids, const int* __restrict__ job_idx,
       const float* __restrict__ W1, const float* __restrict__ b1,
       const float* __restrict__ W2, int N, float* __restrict__ out) {
    extern __shared__ unsigned int smem[];
    unsigned int* W1pk = smem;                      // 8*32*36 = 9216 words
    unsigned int* h0s  = W1pk + 8 * 32 * 36;        // TILE*SAW = 8704 words
    float4* pk = (float4*)(h0s + TILE * SAW);       // 16*4 float4
    // final-merge buffers alias dead W1pk space (used only after main loop)
    float*  fM = (float*)W1pk;                       // 256
    double* fE = (double*)(W1pk + 256);              // 256 doubles = 512 words
    double* fS = (double*)(W1pk + 256 + 512);        // 256 doubles
    __shared__ unsigned long long wkey[MAIN_THREADS / 32];
    __shared__ float wM[MAIN_THREADS / 32], wE[MAIN_THREADS / 32], wS[MAIN_THREADS / 32];
    __shared__ int isLast;

    const int t = threadIdx.x;
    const int lane = t & 31;
    const int w = t >> 5;
    const int q = lane & 3;
    const int g = lane >> 2;

    // pack W1 -> bf16x2 fragments
    for (int i = t; i < 8 * 32 * 16 * 2; i += MAIN_THREADS) {
        int c  = i & 1;
        int nt = (i >> 1) & 15;
        int ln = (i >> 5) & 31;
        int ks = (i >> 10) & 7;
        int qq = ln & 3, gg = ln >> 2;
        int k0 = 16 * ks + 2 * qq + 8 * c;
        int col = 8 * nt + gg;
        W1pk[(ks * 32 + ln) * 36 + nt * 2 + c] =
            bf2(W1[k0 * H + col], W1[(k0 + 1) * H + col]);
    }
    if (t < 64) {
        int nt = t >> 2, qq = t & 3;
        int n0 = 8 * nt + 2 * qq;
        pk[nt * 4 + qq] = make_float4(b1[n0], b1[n0 + 1], W2[n0], W2[n0 + 1]);
    }
    __syncthreads();

    const float4 g4 = *(const float4*)(d_g + 4 * lane);
    unsigned long long wmax = 0ull;
    float om = -INFINITY, ose = 0.f, oss = 0.f;

    const int T = (N + TILE - 1) / TILE;
    unsigned int* myh = h0s + (w * WROWS) * SAW;

    for (int tile = blockIdx.x; tile < T; tile += gridDim.x) {
        const int wbase = tile * TILE + w * WROWS;

        // coalesced id preload: lanes 0-15 load m_ids, lanes 16-31 load job_idx
        int idrow = wbase + (lane & 15);
        const int* idsrc = (lane < WROWS) ? m_ids : job_idx;
        int myid = (idrow < N) ? idsrc[idrow] : 0;

        // stage h0 = relu(g + A[m] + B[j]) as bf16x2  (identical to R11)
#pragma unroll 8
        for (int r = 0; r < WROWS; r++) {
            int m = __shfl_sync(0xffffffffu, myid, r);
            int j = __shfl_sync(0xffffffffu, myid, r + 16);
            float4 h = make_float4(0.f, 0.f, 0.f, 0.f);
            if (wbase + r < N) {
                float4 a = *(const float4*)(d_A + m * H + 4 * lane);
                float4 b = *(const float4*)(d_B + j * H + 4 * lane);
                h.x = fmaxf(g4.x + a.x + b.x, 0.f);
                h.y = fmaxf(g4.y + a.y + b.y, 0.f);
                h.z = fmaxf(g4.z + a.z + b.z, 0.f);
                h.w = fmaxf(g4.w + a.w + b.w, 0.f);
            }
            uint2 u = make_uint2(bf2(h.x, h.y), bf2(h.z, h.w));
            *(uint2*)(myh + r * SAW + 2 * lane) = u;
        }
        __syncwarp();

        // layer1 + fused layer2, two n-passes of 8 n-tiles (32 accum regs)
        float p0 = 0.f, p1 = 0.f;
#pragma unroll 1
        for (int hv = 0; hv < 2; hv++) {
            float c[8][4];
#pragma unroll
            for (int nt = 0; nt < 8; nt++)
#pragma unroll
                for (int i = 0; i < 4; i++) c[nt][i] = 0.f;

#pragma unroll
            for (int ks = 0; ks < 8; ks++) {
                unsigned af[4];
                const unsigned int* ap = myh + g * SAW + 8 * ks + q;
                af[0] = ap[0];
                af[1] = ap[8 * SAW];
                af[2] = ap[4];
                af[3] = ap[8 * SAW + 4];
                const uint4* bp =
                    (const uint4*)(W1pk + (ks * 32 + lane) * 36) + hv * 4;
#pragma unroll
                for (int np = 0; np < 4; np++) {
                    uint4 bv = bp[np];
                    mma_bf16(c[2 * np],     af, bv.x, bv.y);
                    mma_bf16(c[2 * np + 1], af, bv.z, bv.w);
                }
            }
            // partial epilogue over this half's 64 columns
#pragma unroll
            for (int ntl = 0; ntl < 8; ntl++) {
                float4 v = pk[(8 * hv + ntl) * 4 + q];
                p0 += fmaxf(c[ntl][0] + v.x, 0.f) * v.z
                    + fmaxf(c[ntl][1] + v.y, 0.f) * v.w;
                p1 += fmaxf(c[ntl][2] + v.x, 0.f) * v.z
                    + fmaxf(c[ntl][3] + v.y, 0.f) * v.w;
            }
        }

        // quad reduce + online softmax
        p0 += __shfl_xor_sync(0xffffffffu, p0, 1);
        p0 += __shfl_xor_sync(0xffffffffu, p0, 2);
        p1 += __shfl_xor_sync(0xffffffffu, p1, 1);
        p1 += __shfl_xor_sync(0xffffffffu, p1, 2);
        if (q == 0) {
            int r0 = wbase + g;
            if (r0 < N) {
                unsigned long long key =
                    ((unsigned long long)fkey(p0) << 32) |
                    (unsigned long long)(~(unsigned int)r0);
                if (key > wmax) wmax = key;
                if (p0 > om) {
                    float cc = expf(om - p0);
                    ose = ose * cc + 1.f;
                    oss = oss * cc + p0;
                    om = p0;
                } else {
                    float e = expf(p0 - om);
                    ose += e; oss += p0 * e;
                }
            }
            int r1 = r0 + 8;
            if (r1 < N) {
                unsigned long long key =
                    ((unsigned long long)fkey(p1) << 32) |
                    (unsigned long long)(~(unsigned int)r1);
                if (key > wmax) wmax = key;
                if (p1 > om) {
                    float cc = expf(om - p1);
                    ose = ose * cc + 1.f;
                    oss = oss * cc + p1;
                    om = p1;
                } else {
                    float e = expf(p1 - om);
                    ose += e; oss += p1 * e;
                }
            }
        }
        __syncwarp();
    }

    // warp reduce
#pragma unroll
    for (int off = 16; off > 0; off >>= 1) {
        unsigned long long o = __shfl_xor_sync(0xffffffffu, wmax, off);
        if (o > wmax) wmax = o;
        float m2  = __shfl_xor_sync(0xffffffffu, om, off);
        float se2 = __shfl_xor_sync(0xffffffffu, ose, off);
        float ss2 = __shfl_xor_sync(0xffffffffu, oss, off);
        osm_merge(om, ose, oss, m2, se2, ss2);
    }
    if (lane == 0) { wkey[w] = wmax; wM[w] = om; wE[w] = ose; wS[w] = oss; }
    __syncthreads();
    if (t == 0) {
        unsigned long long k = wkey[0];
        float M = wM[0], E = wE[0], S = wS[0];
#pragma unroll
        for (int i = 1; i < MAIN_THREADS / 32; i++) {
            if (wkey[i] > k) k = wkey[i];
            osm_merge(M, E, S, wM[i], wE[i], wS[i]);
        }
        atomicMax(&d_maxkey, k);
        d_blkM[blockIdx.x] = M;
        d_blkE[blockIdx.x] = E;
        d_blkS[blockIdx.x] = S;
        __threadfence();
        unsigned prev = atomicAdd(&d_ticket, 1u);
        isLast = (prev == gridDim.x - 1u);
    }
    __syncthreads();

    // last block merges all block triples and writes the 4 outputs
    if (isLast) {
        float M = -INFINITY; double E = 0.0, S = 0.0;
        for (int i = t; i < (int)gridDim.x; i += MAIN_THREADS) {
            float m2 = d_blkM[i];
            double e2 = d_blkE[i], s2 = d_blkS[i];
            float Mx = fmaxf(M, (e2 > 0.0) ? m2 : M);
            if (m2 > Mx && e2 > 0.0) Mx = m2;
            double a1 = (E > 0.0) ? exp((double)(M - Mx)) : 0.0;
            double a2 = (e2 > 0.0) ? exp((double)(m2 - Mx)) : 0.0;
            E = E * a1 + e2 * a2;
            S = S * a1 + s2 * a2;
            M = Mx;
        }
        fM[t] = M; fE[t] = E; fS[t] = S;
        __syncthreads();
        for (int o = MAIN_THREADS / 2; o > 0; o >>= 1) {
            if (t < o) {
                float m1 = fM[t], m2 = fM[t + o];
                double e1 = fE[t], e2 = fE[t + o];
                double s1 = fS[t], s2 = fS[t + o];
                float Mx = fmaxf((e1 > 0.0) ? m1 : -INFINITY,
                                 (e2 > 0.0) ? m2 : -INFINITY);
                double a1 = (e1 > 0.0) ? exp((double)(m1 - Mx)) : 0.0;
                double a2 = (e2 > 0.0) ? exp((double)(m2 - Mx)) : 0.0;
                fM[t] = Mx;
                fE[t] = e1 * a1 + e2 * a2;
                fS[t] = s1 * a1 + s2 * a2;
            }
            __syncthreads();
        }
        if (t == 0) {
            unsigned long long key = d_maxkey;
            unsigned int idx = ~(unsigned int)(key & 0xffffffffu);
            double sumexp = fE[0];
            double sums = fS[0];
            double lg = log(sumexp);
            out[0] = (float)idx;
            out[1] = (float)(1.0 / sumexp);
            out[2] = (float)(-lg);
            out[3] = (float)((double)fM[0] + lg - sums / sumexp);
        }
    }
}

extern "C" void kernel_launch(void* const* d_in, const int* in_sizes, int n_in,
                              void* d_out, int out_size) {
    const float* x_graph = (const float*)d_in[0];
    const float* x_m     = (const float*)d_in[1];
    const float* x_job   = (const float*)d_in[2];
    const int*   m_ids   = (const int*)d_in[3];
    const int*   job_idx = (const int*)d_in[4];
    const float* W0      = (const float*)d_in[5];
    const float* b0      = (const float*)d_in[6];
    const float* W1      = (const float*)d_in[7];
    const float* b1      = (const float*)d_in[8];
    const float* W2      = (const float*)d_in[9];
    float* out = (float*)d_out;

    int M = in_sizes[1] / H;
    int J = in_sizes[2] / H;
    int N = in_sizes[3];
    if (M > MAXM) M = MAXM;
    if (J > MAXJ) J = MAXJ;

    int blocksA = (M + PREROWS - 1) / PREROWS;
    int blocksB = (J + PREROWS - 1) / PREROWS;
    k_pre<<<blocksA + blocksB + 1, H>>>(x_graph, x_m, x_job, W0, b0, M, J);

    const int smem_main =
        (8 * 32 * 36 + TILE * SAW + 16 * 4 * 4) * (int)sizeof(float);
    static int smem_set = 0;
    if (!smem_set) {
        cudaFuncSetAttribute(k_main, cudaFuncAttributeMaxDynamicSharedMemorySize,
                             smem_main);
        smem_set = 1;
    }
    k_main<<<MAIN_BLOCKS, MAIN_THREADS, smem_main>>>(m_ids, job_idx, W1, b1, W2,
                                                     N, out);
}

// round 14
// speedup vs baseline: 1.0494x; 1.0494x over previous
#include <cuda_runtime.h>
#include <cuda_bf16.h>
#include <math.h>

#define H 128
#define MAXM 2048
#define MAXJ 8192
#define MAIN_BLOCKS 296
#define MAIN_THREADS 256
#define WROWS 16                   // rows per warp
#define TILE (8 * WROWS)           // 128 ops per block-iteration
#define SAW 68                     // h0 smem row stride in 32-bit words

// -------- device scratch --------
__device__ float d_g[H];
__device__ float d_A[MAXM * H];
__device__ float d_B[MAXJ * H];
__device__ unsigned long long d_maxkey;        // zero-init; reset by last block
__device__ unsigned int d_tick_pre;            // pre-phase barrier counter
__device__ unsigned int d_ticket;              // completion counter
__device__ float d_blkM[MAIN_BLOCKS];
__device__ float d_blkE[MAIN_BLOCKS];
__device__ float d_blkS[MAIN_BLOCKS];

__device__ __forceinline__ unsigned int fkey(float f) {
    unsigned int b = __float_as_uint(f);
    return (b & 0x80000000u) ? ~b : (b | 0x80000000u);
}

__device__ __forceinline__ unsigned int bf2(float lo, float hi) {
    __nv_bfloat162 v = __float22bfloat162_rn(make_float2(lo, hi));
    return *(unsigned int*)&v;
}

__device__ __forceinline__ void mma_bf16(float c[4], const unsigned a[4],
                                         unsigned b0, unsigned b1) {
    asm volatile(
        "mma.sync.aligned.m16n8k16.row.col.f32.bf16.bf16.f32 "
        "{%0,%1,%2,%3}, {%4,%5,%6,%7}, {%8,%9}, {%0,%1,%2,%3};"
        : "+f"(c[0]), "+f"(c[1]), "+f"(c[2]), "+f"(c[3])
        : "r"(a[0]), "r"(a[1]), "r"(a[2]), "r"(a[3]), "r"(b0), "r"(b1));
}

__device__ __forceinline__ void osm_merge(float& m, float& se, float& ss,
                                          float m2, float se2, float ss2) {
    float M = fmaxf(m, se2 > 0.f ? m2 : m);
    if (m2 > M) M = m2;
    float a1 = (se > 0.f) ? expf(m - M) : 0.f;
    float a2 = (se2 > 0.f) ? expf(m2 - M) : 0.f;
    se = se * a1 + se2 * a2;
    ss = ss * a1 + ss2 * a2;
    m = M;
}

// ---------------- fused kernel: pre + grid barrier + main + merge ----------------
__global__ void __launch_bounds__(MAIN_THREADS, 2)
k_all(const float* __restrict__ xg,
      const float* __restrict__ xm,
      const float* __restrict__ xj,
      const float* __restrict__ W0,
      const float* __restrict__ b0,
      const int* __restrict__ m_ids, const int* __restrict__ job_idx,
      const float* __restrict__ W1, const float* __restrict__ b1,
      const float* __restrict__ W2,
      int M, int J, int N, float* __restrict__ out) {
    extern __shared__ unsigned int smem[];
    unsigned int* W1pk = smem;                      // 8*32*36 = 9216 words
    unsigned int* h0s  = W1pk + 8 * 32 * 36;        // TILE*SAW = 8704 words
    float4* pk = (float4*)(h0s + TILE * SAW);       // 16*4 float4 = 256 words
    float* sst = (float*)h0s;                       // pre staging (4096 words, aliases h0s)
    __shared__ unsigned long long wkey[MAIN_THREADS / 32];
    __shared__ float wM[MAIN_THREADS / 32], wE[MAIN_THREADS / 32], wS[MAIN_THREADS / 32];
    __shared__ int isLast;
    __shared__ double fE[MAIN_THREADS], fS[MAIN_THREADS];
    __shared__ float fM[MAIN_THREADS];

    const int t = threadIdx.x;
    const int lane = t & 31;
    const int w = t >> 5;
    const int q = lane & 3;
    const int g = lane >> 2;

    // ================= PRE PHASE =================
    const int nA = (M + 31) / 32;
    const int nB = (J + 31) / 32;
    const int nUnits = nA + nB;
    const int nWork = (int)gridDim.x - 1;   // blocks 0..294 do units; 295 does g

    if ((int)blockIdx.x == (int)gridDim.x - 1) {
        // g = x_graph @ W0[0:2H] + b0  (threads 0..127)
        if (t < 2 * H) sst[t] = xg[t];
        __syncthreads();
        if (t < H) {
            float acc = b0[t];
            const float* Wg = W0 + t;
#pragma unroll 1
            for (int k0 = 0; k0 < 2 * H; k0 += 8) {
                float wv[8];
#pragma unroll
                for (int u = 0; u < 8; u++) wv[u] = Wg[(k0 + u) * H];
#pragma unroll
                for (int u = 0; u < 8; u++) acc += sst[k0 + u] * wv[u];
            }
            d_g[t] = acc;
        }
    } else {
        for (int unit = blockIdx.x; unit < nUnits; unit += nWork) {
            bool isA = unit < nA;
            int row0 = (isA ? unit : unit - nA) * 32;
            const float* src = isA ? xm : xj;
            int rows = isA ? M : J;
            int off = isA ? 2 * H : 3 * H;
            float* dst = isA ? d_A : d_B;
            int nrows = min(32, rows - row0);

            __syncthreads();   // protect sst reuse across units
            for (int i = t; i < 32 * H; i += MAIN_THREADS) {
                int r = i >> 7;
                sst[i] = (r < nrows) ? src[(row0 + r) * H + (i & 127)] : 0.f;
            }
            __syncthreads();

            int col = t & 127;
            int rbase = (t >> 7) * 16;
            float acc[16];
#pragma unroll
            for (int r = 0; r < 16; r++) acc[r] = 0.f;
            const float* Wp = W0 + off * H + col;
#pragma unroll 1
            for (int k0 = 0; k0 < H; k0 += 8) {
                float wv[8];
#pragma unroll
                for (int u = 0; u < 8; u++) wv[u] = Wp[(k0 + u) * H];
#pragma unroll
                for (int u = 0; u < 8; u++) {
#pragma unroll
                    for (int r = 0; r < 16; r++)
                        acc[r] += sst[(rbase + r) * H + k0 + u] * wv[u];
                }
            }
            for (int r = 0; r < 16; r++)
                if (rbase + r < nrows)
                    dst[(row0 + rbase + r) * H + col] = acc[r];
        }
    }
    __syncthreads();
    if (t == 0) {
        __threadfence();
        atomicAdd(&d_tick_pre, 1u);
    }

    // pack W1 -> bf16x2 fragments (overlaps other blocks' pre work)
    for (int i = t; i < 8 * 32 * 16 * 2; i += MAIN_THREADS) {
        int c  = i & 1;
        int nt = (i >> 1) & 15;
        int ln = (i >> 5) & 31;
        int ks = (i >> 10) & 7;
        int qq = ln & 3, gg = ln >> 2;
        int k0 = 16 * ks + 2 * qq + 8 * c;
        int col = 8 * nt + gg;
        W1pk[(ks * 32 + ln) * 36 + nt * 2 + c] =
            bf2(W1[k0 * H + col], W1[(k0 + 1) * H + col]);
    }
    if (t < 64) {
        int nt = t >> 2, qq = t & 3;
        int n0 = 8 * nt + 2 * qq;
        pk[nt * 4 + qq] = make_float4(b1[n0], b1[n0 + 1], W2[n0], W2[n0 + 1]);
    }

    // ================= GRID BARRIER =================
    if (t == 0) {
        volatile unsigned int* vp = &d_tick_pre;
        while (*vp < gridDim.x) __nanosleep(64);
    }
    __syncthreads();
    __threadfence();   // acquire d_A/d_B/d_g

    // ================= MAIN PHASE (identical to R11) =================
    const float4 g4 = *(const float4*)(d_g + 4 * lane);
    unsigned long long wmax = 0ull;
    float om = -INFINITY, ose = 0.f, oss = 0.f;

    const int T = (N + TILE - 1) / TILE;
    unsigned int* myh = h0s + (w * WROWS) * SAW;

    for (int tile = blockIdx.x; tile < T; tile += gridDim.x) {
        const int wbase = tile * TILE + w * WROWS;

        // coalesced id preload: lanes 0-15 load m_ids, lanes 16-31 load job_idx
        int idrow = wbase + (lane & 15);
        const int* idsrc = (lane < WROWS) ? m_ids : job_idx;
        int myid = (idrow < N) ? idsrc[idrow] : 0;

        // stage h0 = relu(g + A[m] + B[j]) as bf16x2
#pragma unroll 8
        for (int r = 0; r < WROWS; r++) {
            int m = __shfl_sync(0xffffffffu, myid, r);
            int j = __shfl_sync(0xffffffffu, myid, r + 16);
            float4 h = make_float4(0.f, 0.f, 0.f, 0.f);
            if (wbase + r < N) {
                float4 a = *(const float4*)(d_A + m * H + 4 * lane);
                float4 b = *(const float4*)(d_B + j * H + 4 * lane);
                h.x = fmaxf(g4.x + a.x + b.x, 0.f);
                h.y = fmaxf(g4.y + a.y + b.y, 0.f);
                h.z = fmaxf(g4.z + a.z + b.z, 0.f);
                h.w = fmaxf(g4.w + a.w + b.w, 0.f);
            }
            uint2 u = make_uint2(bf2(h.x, h.y), bf2(h.z, h.w));
            *(uint2*)(myh + r * SAW + 2 * lane) = u;
        }
        __syncwarp();

        // layer1 bf16 MMA: 1 row-tile x 16 n-tiles, K=128 in 8 k16-steps
        float c[16][4];
#pragma unroll
        for (int nt = 0; nt < 16; nt++)
#pragma unroll
            for (int i = 0; i < 4; i++) c[nt][i] = 0.f;

#pragma unroll
        for (int ks = 0; ks < 8; ks++) {
            unsigned af[4];
            const unsigned int* ap = myh + g * SAW + 8 * ks + q;
            af[0] = ap[0];
            af[1] = ap[8 * SAW];
            af[2] = ap[4];
            af[3] = ap[8 * SAW + 4];
            const uint4* bp = (const uint4*)(W1pk + (ks * 32 + lane) * 36);
#pragma unroll
            for (int np = 0; np < 8; np++) {
                uint4 bv = bp[np];
                mma_bf16(c[2 * np],     af, bv.x, bv.y);
                mma_bf16(c[2 * np + 1], af, bv.z, bv.w);
            }
        }

        // fused layer2 + online softmax
        {
            float p0 = 0.f, p1 = 0.f;
#pragma unroll
            for (int nt = 0; nt < 16; nt++) {
                float4 v = pk[nt * 4 + q];
                p0 += fmaxf(c[nt][0] + v.x, 0.f) * v.z
                    + fmaxf(c[nt][1] + v.y, 0.f) * v.w;
                p1 += fmaxf(c[nt][2] + v.x, 0.f) * v.z
                    + fmaxf(c[nt][3] + v.y, 0.f) * v.w;
            }
            p0 += __shfl_xor_sync(0xffffffffu, p0, 1);
            p0 += __shfl_xor_sync(0xffffffffu, p0, 2);
            p1 += __shfl_xor_sync(0xffffffffu, p1, 1);
            p1 += __shfl_xor_sync(0xffffffffu, p1, 2);
            if (q == 0) {
                int r0 = wbase + g;
                if (r0 < N) {
                    unsigned long long key =
                        ((unsigned long long)fkey(p0) << 32) |
                        (unsigned long long)(~(unsigned int)r0);
                    if (key > wmax) wmax = key;
                    if (p0 > om) {
                        float cc = expf(om - p0);
                        ose = ose * cc + 1.f;
                        oss = oss * cc + p0;
                        om = p0;
                    } else {
                        float e = expf(p0 - om);
                        ose += e; oss += p0 * e;
                    }
                }
                int r1 = r0 + 8;
                if (r1 < N) {
                    unsigned long long key =
                        ((unsigned long long)fkey(p1) << 32) |
                        (unsigned long long)(~(unsigned int)r1);
                    if (key > wmax) wmax = key;
                    if (p1 > om) {
                        float cc = expf(om - p1);
                        ose = ose * cc + 1.f;
                        oss = oss * cc + p1;
                        om = p1;
                    } else {
                        float e = expf(p1 - om);
                        ose += e; oss += p1 * e;
                    }
                }
            }
        }
        __syncwarp();
    }

    // warp reduce
#pragma unroll
    for (int off = 16; off > 0; off >>= 1) {
        unsigned long long o = __shfl_xor_sync(0xffffffffu, wmax, off);
        if (o > wmax) wmax = o;
        float m2  = __shfl_xor_sync(0xffffffffu, om, off);
        float se2 = __shfl_xor_sync(0xffffffffu, ose, off);
        float ss2 = __shfl_xor_sync(0xffffffffu, oss, off);
        osm_merge(om, ose, oss, m2, se2, ss2);
    }
    if (lane == 0) { wkey[w] = wmax; wM[w] = om; wE[w] = ose; wS[w] = oss; }
    __syncthreads();
    if (t == 0) {
        unsigned long long k = wkey[0];
        float M2 = wM[0], E = wE[0], S = wS[0];
#pragma unroll
        for (int i = 1; i < MAIN_THREADS / 32; i++) {
            if (wkey[i] > k) k = wkey[i];
            osm_merge(M2, E, S, wM[i], wE[i], wS[i]);
        }
        atomicMax(&d_maxkey, k);
        d_blkM[blockIdx.x] = M2;
        d_blkE[blockIdx.x] = E;
        d_blkS[blockIdx.x] = S;
        __threadfence();
        unsigned prev = atomicAdd(&d_ticket, 1u);
        isLast = (prev == gridDim.x - 1u);
    }
    __syncthreads();

    // last block merges all block triples, writes outputs, resets counters
    if (isLast) {
        float Mm = -INFINITY; double E = 0.0, S = 0.0;
        for (int i = t; i < (int)gridDim.x; i += MAIN_THREADS) {
            float m2 = d_blkM[i];
            double e2 = d_blkE[i], s2 = d_blkS[i];
            float Mx = fmaxf(Mm, (e2 > 0.0) ? m2 : Mm);
            if (m2 > Mx && e2 > 0.0) Mx = m2;
            double a1 = (E > 0.0) ? exp((double)(Mm - Mx)) : 0.0;
            double a2 = (e2 > 0.0) ? exp((double)(m2 - Mx)) : 0.0;
            E = E * a1 + e2 * a2;
            S = S * a1 + s2 * a2;
            Mm = Mx;
        }
        fM[t] = Mm; fE[t] = E; fS[t] = S;
        __syncthreads();
        for (int o = MAIN_THREADS / 2; o > 0; o >>= 1) {
            if (t < o) {
                float m1 = fM[t], m2 = fM[t + o];
                double e1 = fE[t], e2 = fE[t + o];
                double s1 = fS[t], s2 = fS[t + o];
                float Mx = fmaxf((e1 > 0.0) ? m1 : -INFINITY,
                                 (e2 > 0.0) ? m2 : -INFINITY);
                double a1 = (e1 > 0.0) ? exp((double)(m1 - Mx)) : 0.0;
                double a2 = (e2 > 0.0) ? exp((double)(m2 - Mx)) : 0.0;
                fM[t] = Mx;
                fE[t] = e1 * a1 + e2 * a2;
                fS[t] = s1 * a1 + s2 * a2;
            }
            __syncthreads();
        }
        if (t == 0) {
            unsigned long long key = d_maxkey;
            unsigned int idx = ~(unsigned int)(key & 0xffffffffu);
            double sumexp = fE[0];
            double sums = fS[0];
            double lg = log(sumexp);
            out[0] = (float)idx;
            out[1] = (float)(1.0 / sumexp);
            out[2] = (float)(-lg);
            out[3] = (float)((double)fM[0] + lg - sums / sumexp);
            // reset counters for next graph replay (deterministic)
            d_maxkey = 0ull;
            d_tick_pre = 0u;
            d_ticket = 0u;
            __threadfence();
        }
    }
}

extern "C" void kernel_launch(void* const* d_in, const int* in_sizes, int n_in,
                              void* d_out, int out_size) {
    const float* x_graph = (const float*)d_in[0];
    const float* x_m     = (const float*)d_in[1];
    const float* x_job   = (const float*)d_in[2];
    const int*   m_ids   = (const int*)d_in[3];
    const int*   job_idx = (const int*)d_in[4];
    const float* W0      = (const float*)d_in[5];
    const float* b0      = (const float*)d_in[6];
    const float* W1      = (const float*)d_in[7];
    const float* b1      = (const float*)d_in[8];
    const float* W2      = (const float*)d_in[9];
    float* out = (float*)d_out;

    int M = in_sizes[1] / H;
    int J = in_sizes[2] / H;
    int N = in_sizes[3];
    if (M > MAXM) M = MAXM;
    if (J > MAXJ) J = MAXJ;

    const int smem_main =
        (8 * 32 * 36 + TILE * SAW + 16 * 4 * 4) * (int)sizeof(float);
    static int smem_set = 0;
    if (!smem_set) {
        cudaFuncSetAttribute(k_all, cudaFuncAttributeMaxDynamicSharedMemorySize,
                             smem_main);
        smem_set = 1;
    }
    k_all<<<MAIN_BLOCKS, MAIN_THREADS, smem_main>>>(
        x_graph, x_m, x_job, W0, b0, m_ids, job_idx, W1, b1, W2, M, J, N, out);
}

// round 15
// speedup vs baseline: 1.0844x; 1.0333x over previous
#include <cuda_runtime.h>
#include <cuda_bf16.h>
#include <math.h>

#define H 128
#define MAXM 2048
#define MAXJ 8192
#define MAIN_BLOCKS 296
#define MAIN_THREADS 256
#define WROWS 16                   // rows per warp
#define TILE (8 * WROWS)           // 128 ops per block-iteration
#define SAW 68                     // h0 smem row stride in 32-bit words

// -------- device scratch --------
__device__ float d_g[H];
__device__ float d_A[MAXM * H];
__device__ float d_B[MAXJ * H];
__device__ unsigned long long d_maxkey;        // zero-init; reset by last block
__device__ unsigned int d_tick_pre;            // pre-phase barrier counter
__device__ unsigned int d_ticket;              // completion counter
__device__ float d_blkM[MAIN_BLOCKS];
__device__ float d_blkE[MAIN_BLOCKS];
__device__ float d_blkS[MAIN_BLOCKS];

__device__ __forceinline__ unsigned int fkey(float f) {
    unsigned int b = __float_as_uint(f);
    return (b & 0x80000000u) ? ~b : (b | 0x80000000u);
}

__device__ __forceinline__ unsigned int bf2(float lo, float hi) {
    __nv_bfloat162 v = __float22bfloat162_rn(make_float2(lo, hi));
    return *(unsigned int*)&v;
}

__device__ __forceinline__ void mma_bf16(float c[4], const unsigned a[4],
                                         unsigned b0, unsigned b1) {
    asm volatile(
        "mma.sync.aligned.m16n8k16.row.col.f32.bf16.bf16.f32 "
        "{%0,%1,%2,%3}, {%4,%5,%6,%7}, {%8,%9}, {%0,%1,%2,%3};"
        : "+f"(c[0]), "+f"(c[1]), "+f"(c[2]), "+f"(c[3])
        : "r"(a[0]), "r"(a[1]), "r"(a[2]), "r"(a[3]), "r"(b0), "r"(b1));
}

__device__ __forceinline__ void osm_merge(float& m, float& se, float& ss,
                                          float m2, float se2, float ss2) {
    float M = fmaxf(m, se2 > 0.f ? m2 : m);
    if (m2 > M) M = m2;
    float a1 = (se > 0.f) ? expf(m - M) : 0.f;
    float a2 = (se2 > 0.f) ? expf(m2 - M) : 0.f;
    se = se * a1 + se2 * a2;
    ss = ss * a1 + ss2 * a2;
    m = M;
}

// ---------------- fused kernel: MMA pre + grid barrier + main + merge ----------------
__global__ void __launch_bounds__(MAIN_THREADS, 2)
k_all(const float* __restrict__ xg,
      const float* __restrict__ xm,
      const float* __restrict__ xj,
      const float* __restrict__ W0,
      const float* __restrict__ b0,
      const int* __restrict__ m_ids, const int* __restrict__ job_idx,
      const float* __restrict__ W1, const float* __restrict__ b1,
      const float* __restrict__ W2,
      int M, int J, int N, float* __restrict__ out) {
    extern __shared__ unsigned int smem[];
    unsigned int* W1pk = smem;                      // 8*32*36 = 9216 words (W0pk in pre)
    unsigned int* h0s  = W1pk + 8 * 32 * 36;        // TILE*SAW = 8704 words
    float4* pk = (float4*)(h0s + TILE * SAW);       // 16*4 float4 = 256 words
    float* sst = (float*)h0s;                       // g staging (aliases h0s)
    __shared__ unsigned long long wkey[MAIN_THREADS / 32];
    __shared__ float wM[MAIN_THREADS / 32], wE[MAIN_THREADS / 32], wS[MAIN_THREADS / 32];
    __shared__ int isLast;
    __shared__ double fE[MAIN_THREADS], fS[MAIN_THREADS];
    __shared__ float fM[MAIN_THREADS];

    const int t = threadIdx.x;
    const int lane = t & 31;
    const int w = t >> 5;
    const int q = lane & 3;
    const int g = lane >> 2;
    unsigned int* myh = h0s + (w * WROWS) * SAW;

    // ================= PRE PHASE =================
    const int nA = (M + 127) / 128;
    const int nB = (J + 127) / 128;
    const int nUnits = nA + nB;

    if ((int)blockIdx.x == (int)gridDim.x - 1) {
        // g = x_graph @ W0[0:2H] + b0  (threads 0..127)
        if (t < 2 * H) sst[t] = xg[t];
        __syncthreads();
        if (t < H) {
            float acc = b0[t];
            const float* Wg = W0 + t;
#pragma unroll 1
            for (int k0 = 0; k0 < 2 * H; k0 += 8) {
                float wv[8];
#pragma unroll
                for (int u = 0; u < 8; u++) wv[u] = Wg[(k0 + u) * H];
#pragma unroll
                for (int u = 0; u < 8; u++) acc += sst[k0 + u] * wv[u];
            }
            d_g[t] = acc;
        }
        __syncthreads();
    } else if ((int)blockIdx.x < nUnits) {
        // one 128-row bf16 MMA unit: dst[row0:row0+128] = x @ W0_slab
        bool isA = (int)blockIdx.x < nA;
        int row0 = (isA ? (int)blockIdx.x : (int)blockIdx.x - nA) * 128;
        const float* src = isA ? xm : xj;
        int rows = isA ? M : J;
        const float* Ws = W0 + (isA ? 2 * H : 3 * H) * H;
        float* dst = isA ? d_A : d_B;

        // pack W0 slab -> W1pk region (same fragment layout as W1 pack)
        for (int i = t; i < 8 * 32 * 16 * 2; i += MAIN_THREADS) {
            int c  = i & 1;
            int nt = (i >> 1) & 15;
            int ln = (i >> 5) & 31;
            int ks = (i >> 10) & 7;
            int qq = ln & 3, gg = ln >> 2;
            int k0 = 16 * ks + 2 * qq + 8 * c;
            int col = 8 * nt + gg;
            W1pk[(ks * 32 + ln) * 36 + nt * 2 + c] =
                bf2(Ws[k0 * H + col], Ws[(k0 + 1) * H + col]);
        }
        __syncthreads();

        // stage 16 x-rows per warp as bf16 (no gather, no relu, no g)
#pragma unroll 8
        for (int r = 0; r < WROWS; r++) {
            int row = row0 + w * WROWS + r;
            float4 h = make_float4(0.f, 0.f, 0.f, 0.f);
            if (row < rows) h = *(const float4*)(src + row * H + 4 * lane);
            uint2 u = make_uint2(bf2(h.x, h.y), bf2(h.z, h.w));
            *(uint2*)(myh + r * SAW + 2 * lane) = u;
        }
        __syncwarp();

        // same MMA loop as main
        float c[16][4];
#pragma unroll
        for (int nt = 0; nt < 16; nt++)
#pragma unroll
            for (int i = 0; i < 4; i++) c[nt][i] = 0.f;
#pragma unroll
        for (int ks = 0; ks < 8; ks++) {
            unsigned af[4];
            const unsigned int* ap = myh + g * SAW + 8 * ks + q;
            af[0] = ap[0];
            af[1] = ap[8 * SAW];
            af[2] = ap[4];
            af[3] = ap[8 * SAW + 4];
            const uint4* bp = (const uint4*)(W1pk + (ks * 32 + lane) * 36);
#pragma unroll
            for (int np = 0; np < 8; np++) {
                uint4 bv = bp[np];
                mma_bf16(c[2 * np],     af, bv.x, bv.y);
                mma_bf16(c[2 * np + 1], af, bv.z, bv.w);
            }
        }

        // store fp32 accumulators (m16n8 layout: rows g / g+8, cols 8nt+2q..+1)
        int r0 = row0 + w * WROWS + g;
        int r1 = r0 + 8;
#pragma unroll
        for (int nt = 0; nt < 16; nt++) {
            int col = 8 * nt + 2 * q;
            if (r0 < rows) *(float2*)(dst + r0 * H + col) = make_float2(c[nt][0], c[nt][1]);
            if (r1 < rows) *(float2*)(dst + r1 * H + col) = make_float2(c[nt][2], c[nt][3]);
        }
        __syncthreads();
    }
    __threadfence();
    __syncthreads();
    if (t == 0) atomicAdd(&d_tick_pre, 1u);

    // ================= GRID BARRIER =================
    if (t == 0) {
        volatile unsigned int* vp = &d_tick_pre;
        while (*vp < gridDim.x) __nanosleep(64);
    }
    __syncthreads();
    __threadfence();   // acquire d_A/d_B/d_g

    // pack W1 -> bf16x2 fragments (overwrites W0pk)
    for (int i = t; i < 8 * 32 * 16 * 2; i += MAIN_THREADS) {
        int c  = i & 1;
        int nt = (i >> 1) & 15;
        int ln = (i >> 5) & 31;
        int ks = (i >> 10) & 7;
        int qq = ln & 3, gg = ln >> 2;
        int k0 = 16 * ks + 2 * qq + 8 * c;
        int col = 8 * nt + gg;
        W1pk[(ks * 32 + ln) * 36 + nt * 2 + c] =
            bf2(W1[k0 * H + col], W1[(k0 + 1) * H + col]);
    }
    if (t < 64) {
        int nt = t >> 2, qq = t & 3;
        int n0 = 8 * nt + 2 * qq;
        pk[nt * 4 + qq] = make_float4(b1[n0], b1[n0 + 1], W2[n0], W2[n0 + 1]);
    }
    __syncthreads();

    // ================= MAIN PHASE (identical to R14) =================
    const float4 g4 = *(const float4*)(d_g + 4 * lane);
    unsigned long long wmax = 0ull;
    float om = -INFINITY, ose = 0.f, oss = 0.f;

    const int T = (N + TILE - 1) / TILE;

    for (int tile = blockIdx.x; tile < T; tile += gridDim.x) {
        const int wbase = tile * TILE + w * WROWS;

        // coalesced id preload: lanes 0-15 load m_ids, lanes 16-31 load job_idx
        int idrow = wbase + (lane & 15);
        const int* idsrc = (lane < WROWS) ? m_ids : job_idx;
        int myid = (idrow < N) ? idsrc[idrow] : 0;

        // stage h0 = relu(g + A[m] + B[j]) as bf16x2
#pragma unroll 8
        for (int r = 0; r < WROWS; r++) {
            int m = __shfl_sync(0xffffffffu, myid, r);
            int j = __shfl_sync(0xffffffffu, myid, r + 16);
            float4 h = make_float4(0.f, 0.f, 0.f, 0.f);
            if (wbase + r < N) {
                float4 a = *(const float4*)(d_A + m * H + 4 * lane);
                float4 b = *(const float4*)(d_B + j * H + 4 * lane);
                h.x = fmaxf(g4.x + a.x + b.x, 0.f);
                h.y = fmaxf(g4.y + a.y + b.y, 0.f);
                h.z = fmaxf(g4.z + a.z + b.z, 0.f);
                h.w = fmaxf(g4.w + a.w + b.w, 0.f);
            }
            uint2 u = make_uint2(bf2(h.x, h.y), bf2(h.z, h.w));
            *(uint2*)(myh + r * SAW + 2 * lane) = u;
        }
        __syncwarp();

        // layer1 bf16 MMA: 1 row-tile x 16 n-tiles, K=128 in 8 k16-steps
        float c[16][4];
#pragma unroll
        for (int nt = 0; nt < 16; nt++)
#pragma unroll
            for (int i = 0; i < 4; i++) c[nt][i] = 0.f;

#pragma unroll
        for (int ks = 0; ks < 8; ks++) {
            unsigned af[4];
            const unsigned int* ap = myh + g * SAW + 8 * ks + q;
            af[0] = ap[0];
            af[1] = ap[8 * SAW];
            af[2] = ap[4];
            af[3] = ap[8 * SAW + 4];
            const uint4* bp = (const uint4*)(W1pk + (ks * 32 + lane) * 36);
#pragma unroll
            for (int np = 0; np < 8; np++) {
                uint4 bv = bp[np];
                mma_bf16(c[2 * np],     af, bv.x, bv.y);
                mma_bf16(c[2 * np + 1], af, bv.z, bv.w);
            }
        }

        // fused layer2 + online softmax
        {
            float p0 = 0.f, p1 = 0.f;
#pragma unroll
            for (int nt = 0; nt < 16; nt++) {
                float4 v = pk[nt * 4 + q];
                p0 += fmaxf(c[nt][0] + v.x, 0.f) * v.z
                    + fmaxf(c[nt][1] + v.y, 0.f) * v.w;
                p1 += fmaxf(c[nt][2] + v.x, 0.f) * v.z
                    + fmaxf(c[nt][3] + v.y, 0.f) * v.w;
            }
            p0 += __shfl_xor_sync(0xffffffffu, p0, 1);
            p0 += __shfl_xor_sync(0xffffffffu, p0, 2);
            p1 += __shfl_xor_sync(0xffffffffu, p1, 1);
            p1 += __shfl_xor_sync(0xffffffffu, p1, 2);
            if (q == 0) {
                int r0 = wbase + g;
                if (r0 < N) {
                    unsigned long long key =
                        ((unsigned long long)fkey(p0) << 32) |
                        (unsigned long long)(~(unsigned int)r0);
                    if (key > wmax) wmax = key;
                    if (p0 > om) {
                        float cc = expf(om - p0);
                        ose = ose * cc + 1.f;
                        oss = oss * cc + p0;
                        om = p0;
                    } else {
                        float e = expf(p0 - om);
                        ose += e; oss += p0 * e;
                    }
                }
                int r1 = r0 + 8;
                if (r1 < N) {
                    unsigned long long key =
                        ((unsigned long long)fkey(p1) << 32) |
                        (unsigned long long)(~(unsigned int)r1);
                    if (key > wmax) wmax = key;
                    if (p1 > om) {
                        float cc = expf(om - p1);
                        ose = ose * cc + 1.f;
                        oss = oss * cc + p1;
                        om = p1;
                    } else {
                        float e = expf(p1 - om);
                        ose += e; oss += p1 * e;
                    }
                }
            }
        }
        __syncwarp();
    }

    // warp reduce
#pragma unroll
    for (int off = 16; off > 0; off >>= 1) {
        unsigned long long o = __shfl_xor_sync(0xffffffffu, wmax, off);
        if (o > wmax) wmax = o;
        float m2  = __shfl_xor_sync(0xffffffffu, om, off);
        float se2 = __shfl_xor_sync(0xffffffffu, ose, off);
        float ss2 = __shfl_xor_sync(0xffffffffu, oss, off);
        osm_merge(om, ose, oss, m2, se2, ss2);
    }
    if (lane == 0) { wkey[w] = wmax; wM[w] = om; wE[w] = ose; wS[w] = oss; }
    __syncthreads();
    if (t == 0) {
        unsigned long long k = wkey[0];
        float M2 = wM[0], E = wE[0], S = wS[0];
#pragma unroll
        for (int i = 1; i < MAIN_THREADS / 32; i++) {
            if (wkey[i] > k) k = wkey[i];
            osm_merge(M2, E, S, wM[i], wE[i], wS[i]);
        }
        atomicMax(&d_maxkey, k);
        d_blkM[blockIdx.x] = M2;
        d_blkE[blockIdx.x] = E;
        d_blkS[blockIdx.x] = S;
        __threadfence();
        unsigned prev = atomicAdd(&d_ticket, 1u);
        isLast = (prev == gridDim.x - 1u);
    }
    __syncthreads();

    // last block merges all block triples, writes outputs, resets counters
    if (isLast) {
        float Mm = -INFINITY; double E = 0.0, S = 0.0;
        for (int i = t; i < (int)gridDim.x; i += MAIN_THREADS) {
            float m2 = d_blkM[i];
            double e2 = d_blkE[i], s2 = d_blkS[i];
            float Mx = fmaxf(Mm, (e2 > 0.0) ? m2 : Mm);
            if (m2 > Mx && e2 > 0.0) Mx = m2;
            double a1 = (E > 0.0) ? exp((double)(Mm - Mx)) : 0.0;
            double a2 = (e2 > 0.0) ? exp((double)(m2 - Mx)) : 0.0;
            E = E * a1 + e2 * a2;
            S = S * a1 + s2 * a2;
            Mm = Mx;
        }
        fM[t] = Mm; fE[t] = E; fS[t] = S;
        __syncthreads();
        for (int o = MAIN_THREADS / 2; o > 0; o >>= 1) {
            if (t < o) {
                float m1 = fM[t], m2 = fM[t + o];
                double e1 = fE[t], e2 = fE[t + o];
                double s1 = fS[t], s2 = fS[t + o];
                float Mx = fmaxf((e1 > 0.0) ? m1 : -INFINITY,
                                 (e2 > 0.0) ? m2 : -INFINITY);
                double a1 = (e1 > 0.0) ? exp((double)(m1 - Mx)) : 0.0;
                double a2 = (e2 > 0.0) ? exp((double)(m2 - Mx)) : 0.0;
                fM[t] = Mx;
                fE[t] = e1 * a1 + e2 * a2;
                fS[t] = s1 * a1 + s2 * a2;
            }
            __syncthreads();
        }
        if (t == 0) {
            unsigned long long key = d_maxkey;
            unsigned int idx = ~(unsigned int)(key & 0xffffffffu);
            double sumexp = fE[0];
            double sums = fS[0];
            double lg = log(sumexp);
            out[0] = (float)idx;
            out[1] = (float)(1.0 / sumexp);
            out[2] = (float)(-lg);
            out[3] = (float)((double)fM[0] + lg - sums / sumexp);
            // reset counters for next graph replay (deterministic)
            d_maxkey = 0ull;
            d_tick_pre = 0u;
            d_ticket = 0u;
            __threadfence();
        }
    }
}

extern "C" void kernel_launch(void* const* d_in, const int* in_sizes, int n_in,
                              void* d_out, int out_size) {
    const float* x_graph = (const float*)d_in[0];
    const float* x_m     = (const float*)d_in[1];
    const float* x_job   = (const float*)d_in[2];
    const int*   m_ids   = (const int*)d_in[3];
    const int*   job_idx = (const int*)d_in[4];
    const float* W0      = (const float*)d_in[5];
    const float* b0      = (const float*)d_in[6];
    const float* W1      = (const float*)d_in[7];
    const float* b1      = (const float*)d_in[8];
    const float* W2      = (const float*)d_in[9];
    float* out = (float*)d_out;

    int M = in_sizes[1] / H;
    int J = in_sizes[2] / H;
    int N = in_sizes[3];
    if (M > MAXM) M = MAXM;
    if (J > MAXJ) J = MAXJ;

    const int smem_main =
        (8 * 32 * 36 + TILE * SAW + 16 * 4 * 4) * (int)sizeof(float);
    static int smem_set = 0;
    if (!smem_set) {
        cudaFuncSetAttribute(k_all, cudaFuncAttributeMaxDynamicSharedMemorySize,
                             smem_main);
        smem_set = 1;
    }
    k_all<<<MAIN_BLOCKS, MAIN_THREADS, smem_main>>>(
        x_graph, x_m, x_job, W0, b0, m_ids, job_idx, W1, b1, W2, M, J, N, out);
}

// round 16
// speedup vs baseline: 1.1040x; 1.0180x over previous
#include <cuda_runtime.h>
#include <cuda_fp16.h>
#include <cuda_bf16.h>
#include <math.h>

#define H 128
#define MAXM 2048
#define MAXJ 8192
#define MAIN_BLOCKS 296
#define MAIN_THREADS 256
#define WROWS 16                   // rows per warp
#define TILE (8 * WROWS)           // 128 ops per block-iteration
#define SAW 68                     // h0 smem row stride in 32-bit words

// -------- device scratch --------
__device__ float d_g[H];
__device__ unsigned int d_Ah[MAXM * 64];   // fp16x2 rows of A = x_m@W0[2H:3H]
__device__ unsigned int d_Bh[MAXJ * 64];   // fp16x2 rows of B = x_job@W0[3H:4H]
__device__ unsigned long long d_maxkey;
__device__ unsigned int d_tick_pre;
__device__ unsigned int d_ticket;
__device__ float d_blkM[MAIN_BLOCKS];
__device__ float d_blkE[MAIN_BLOCKS];
__device__ float d_blkS[MAIN_BLOCKS];

__device__ __forceinline__ unsigned int fkey(float f) {
    unsigned int b = __float_as_uint(f);
    return (b & 0x80000000u) ? ~b : (b | 0x80000000u);
}

__device__ __forceinline__ unsigned int bf2(float lo, float hi) {
    __nv_bfloat162 v = __float22bfloat162_rn(make_float2(lo, hi));
    return *(unsigned int*)&v;
}

__device__ __forceinline__ unsigned int hf2(float lo, float hi) {
    __half2 v = __floats2half2_rn(lo, hi);
    return *(unsigned int*)&v;
}

__device__ __forceinline__ void mma_bf16(float c[4], const unsigned a[4],
                                         unsigned b0, unsigned b1) {
    asm volatile(
        "mma.sync.aligned.m16n8k16.row.col.f32.bf16.bf16.f32 "
        "{%0,%1,%2,%3}, {%4,%5,%6,%7}, {%8,%9}, {%0,%1,%2,%3};"
        : "+f"(c[0]), "+f"(c[1]), "+f"(c[2]), "+f"(c[3])
        : "r"(a[0]), "r"(a[1]), "r"(a[2]), "r"(a[3]), "r"(b0), "r"(b1));
}

__device__ __forceinline__ void osm_merge(float& m, float& se, float& ss,
                                          float m2, float se2, float ss2) {
    float M = fmaxf(m, se2 > 0.f ? m2 : m);
    if (m2 > M) M = m2;
    float a1 = (se > 0.f) ? expf(m - M) : 0.f;
    float a2 = (se2 > 0.f) ? expf(m2 - M) : 0.f;
    se = se * a1 + se2 * a2;
    ss = ss * a1 + ss2 * a2;
    m = M;
}

// ---------------- fused kernel: MMA pre + grid barrier + main + merge ----------------
__global__ void __launch_bounds__(MAIN_THREADS, 2)
k_all(const float* __restrict__ xg,
      const float* __restrict__ xm,
      const float* __restrict__ xj,
      const float* __restrict__ W0,
      const float* __restrict__ b0,
      const int* __restrict__ m_ids, const int* __restrict__ job_idx,
      const float* __restrict__ W1, const float* __restrict__ b1,
      const float* __restrict__ W2,
      int M, int J, int N, float* __restrict__ out) {
    extern __shared__ unsigned int smem[];
    unsigned int* W1pk = smem;                      // 8*32*36 = 9216 words (W0pk in pre)
    unsigned int* h0s  = W1pk + 8 * 32 * 36;        // TILE*SAW = 8704 words
    float4* pk = (float4*)(h0s + TILE * SAW);       // 16*4 float4 = 256 words
    float* sst = (float*)h0s;                       // g staging (aliases h0s)
    __shared__ unsigned long long wkey[MAIN_THREADS / 32];
    __shared__ float wM[MAIN_THREADS / 32], wE[MAIN_THREADS / 32], wS[MAIN_THREADS / 32];
    __shared__ int isLast;
    __shared__ double fE[MAIN_THREADS], fS[MAIN_THREADS];
    __shared__ float fM[MAIN_THREADS];

    const int t = threadIdx.x;
    const int lane = t & 31;
    const int w = t >> 5;
    const int q = lane & 3;
    const int g = lane >> 2;
    unsigned int* myh = h0s + (w * WROWS) * SAW;

    // ================= PRE PHASE =================
    const int nA = (M + 127) / 128;
    const int nB = (J + 127) / 128;
    const int nUnits = nA + nB;

    if ((int)blockIdx.x == (int)gridDim.x - 1) {
        // g = x_graph @ W0[0:2H] + b0  (threads 0..127)
        if (t < 2 * H) sst[t] = xg[t];
        __syncthreads();
        if (t < H) {
            float acc = b0[t];
            const float* Wg = W0 + t;
#pragma unroll 1
            for (int k0 = 0; k0 < 2 * H; k0 += 8) {
                float wv[8];
#pragma unroll
                for (int u = 0; u < 8; u++) wv[u] = Wg[(k0 + u) * H];
#pragma unroll
                for (int u = 0; u < 8; u++) acc += sst[k0 + u] * wv[u];
            }
            d_g[t] = acc;
        }
        __syncthreads();
    } else if ((int)blockIdx.x < nUnits) {
        // one 128-row bf16 MMA unit: dst[row0:row0+128] = x @ W0_slab (fp16 store)
        bool isA = (int)blockIdx.x < nA;
        int row0 = (isA ? (int)blockIdx.x : (int)blockIdx.x - nA) * 128;
        const float* src = isA ? xm : xj;
        int rows = isA ? M : J;
        const float* Ws = W0 + (isA ? 2 * H : 3 * H) * H;
        unsigned int* dst = isA ? d_Ah : d_Bh;

        // pack W0 slab -> W1pk region (same fragment layout as W1 pack)
        for (int i = t; i < 8 * 32 * 16 * 2; i += MAIN_THREADS) {
            int c  = i & 1;
            int nt = (i >> 1) & 15;
            int ln = (i >> 5) & 31;
            int ks = (i >> 10) & 7;
            int qq = ln & 3, gg = ln >> 2;
            int k0 = 16 * ks + 2 * qq + 8 * c;
            int col = 8 * nt + gg;
            W1pk[(ks * 32 + ln) * 36 + nt * 2 + c] =
                bf2(Ws[k0 * H + col], Ws[(k0 + 1) * H + col]);
        }
        __syncthreads();

        // stage 16 x-rows per warp as bf16
#pragma unroll 8
        for (int r = 0; r < WROWS; r++) {
            int row = row0 + w * WROWS + r;
            float4 h = make_float4(0.f, 0.f, 0.f, 0.f);
            if (row < rows) h = *(const float4*)(src + row * H + 4 * lane);
            uint2 u = make_uint2(bf2(h.x, h.y), bf2(h.z, h.w));
            *(uint2*)(myh + r * SAW + 2 * lane) = u;
        }
        __syncwarp();

        // same MMA loop as main
        float c[16][4];
#pragma unroll
        for (int nt = 0; nt < 16; nt++)
#pragma unroll
            for (int i = 0; i < 4; i++) c[nt][i] = 0.f;
#pragma unroll
        for (int ks = 0; ks < 8; ks++) {
            unsigned af[4];
            const unsigned int* ap = myh + g * SAW + 8 * ks + q;
            af[0] = ap[0];
            af[1] = ap[8 * SAW];
            af[2] = ap[4];
            af[3] = ap[8 * SAW + 4];
            const uint4* bp = (const uint4*)(W1pk + (ks * 32 + lane) * 36);
#pragma unroll
            for (int np = 0; np < 8; np++) {
                uint4 bv = bp[np];
                mma_bf16(c[2 * np],     af, bv.x, bv.y);
                mma_bf16(c[2 * np + 1], af, bv.z, bv.w);
            }
        }

        // store fp16 accumulators (m16n8 layout: rows g/g+8, cols 8nt+2q..+1)
        int r0 = row0 + w * WROWS + g;
        int r1 = r0 + 8;
#pragma unroll
        for (int nt = 0; nt < 16; nt++) {
            int hw = 4 * nt + q;        // half2 word index = col/2
            if (r0 < rows) dst[r0 * 64 + hw] = hf2(c[nt][0], c[nt][1]);
            if (r1 < rows) dst[r1 * 64 + hw] = hf2(c[nt][2], c[nt][3]);
        }
        __syncthreads();
    }
    __threadfence();
    __syncthreads();
    if (t == 0) atomicAdd(&d_tick_pre, 1u);

    // ================= GRID BARRIER =================
    if (t == 0) {
        volatile unsigned int* vp = &d_tick_pre;
        while (*vp < gridDim.x) __nanosleep(64);
    }
    __syncthreads();
    __threadfence();   // acquire d_Ah/d_Bh/d_g

    // pack W1 -> bf16x2 fragments (overwrites W0pk)
    for (int i = t; i < 8 * 32 * 16 * 2; i += MAIN_THREADS) {
        int c  = i & 1;
        int nt = (i >> 1) & 15;
        int ln = (i >> 5) & 31;
        int ks = (i >> 10) & 7;
        int qq = ln & 3, gg = ln >> 2;
        int k0 = 16 * ks + 2 * qq + 8 * c;
        int col = 8 * nt + gg;
        W1pk[(ks * 32 + ln) * 36 + nt * 2 + c] =
            bf2(W1[k0 * H + col], W1[(k0 + 1) * H + col]);
    }
    if (t < 64) {
        int nt = t >> 2, qq = t & 3;
        int n0 = 8 * nt + 2 * qq;
        pk[nt * 4 + qq] = make_float4(b1[n0], b1[n0 + 1], W2[n0], W2[n0 + 1]);
    }
    __syncthreads();

    // ================= MAIN PHASE =================
    const float4 g4 = *(const float4*)(d_g + 4 * lane);
    unsigned long long wmax = 0ull;
    float om = -INFINITY, ose = 0.f, oss = 0.f;

    const int T = (N + TILE - 1) / TILE;

    for (int tile = blockIdx.x; tile < T; tile += gridDim.x) {
        const int wbase = tile * TILE + w * WROWS;

        // coalesced id preload: lanes 0-15 load m_ids, lanes 16-31 load job_idx
        int idrow = wbase + (lane & 15);
        const int* idsrc = (lane < WROWS) ? m_ids : job_idx;
        int myid = (idrow < N) ? idsrc[idrow] : 0;

        // stage h0 = relu(g + A[m] + B[j]) as bf16x2 (fp16 table loads, fp32 add)
#pragma unroll 8
        for (int r = 0; r < WROWS; r++) {
            int m = __shfl_sync(0xffffffffu, myid, r);
            int j = __shfl_sync(0xffffffffu, myid, r + 16);
            float4 h = make_float4(0.f, 0.f, 0.f, 0.f);
            if (wbase + r < N) {
                uint2 ua = *(const uint2*)(d_Ah + m * 64 + 2 * lane);
                uint2 ub = *(const uint2*)(d_Bh + j * 64 + 2 * lane);
                float2 a0 = __half22float2(*(__half2*)&ua.x);
                float2 a1 = __half22float2(*(__half2*)&ua.y);
                float2 b0v = __half22float2(*(__half2*)&ub.x);
                float2 b1v = __half22float2(*(__half2*)&ub.y);
                h.x = fmaxf(g4.x + a0.x + b0v.x, 0.f);
                h.y = fmaxf(g4.y + a0.y + b0v.y, 0.f);
                h.z = fmaxf(g4.z + a1.x + b1v.x, 0.f);
                h.w = fmaxf(g4.w + a1.y + b1v.y, 0.f);
            }
            uint2 u = make_uint2(bf2(h.x, h.y), bf2(h.z, h.w));
            *(uint2*)(myh + r * SAW + 2 * lane) = u;
        }
        __syncwarp();

        // layer1 bf16 MMA: 1 row-tile x 16 n-tiles, K=128 in 8 k16-steps
        float c[16][4];
#pragma unroll
        for (int nt = 0; nt < 16; nt++)
#pragma unroll
            for (int i = 0; i < 4; i++) c[nt][i] = 0.f;

#pragma unroll
        for (int ks = 0; ks < 8; ks++) {
            unsigned af[4];
            const unsigned int* ap = myh + g * SAW + 8 * ks + q;
            af[0] = ap[0];
            af[1] = ap[8 * SAW];
            af[2] = ap[4];
            af[3] = ap[8 * SAW + 4];
            const uint4* bp = (const uint4*)(W1pk + (ks * 32 + lane) * 36);
#pragma unroll
            for (int np = 0; np < 8; np++) {
                uint4 bv = bp[np];
                mma_bf16(c[2 * np],     af, bv.x, bv.y);
                mma_bf16(c[2 * np + 1], af, bv.z, bv.w);
            }
        }

        // fused layer2 + online softmax
        {
            float p0 = 0.f, p1 = 0.f;
#pragma unroll
            for (int nt = 0; nt < 16; nt++) {
                float4 v = pk[nt * 4 + q];
                p0 += fmaxf(c[nt][0] + v.x, 0.f) * v.z
                    + fmaxf(c[nt][1] + v.y, 0.f) * v.w;
                p1 += fmaxf(c[nt][2] + v.x, 0.f) * v.z
                    + fmaxf(c[nt][3] + v.y, 0.f) * v.w;
            }
            p0 += __shfl_xor_sync(0xffffffffu, p0, 1);
            p0 += __shfl_xor_sync(0xffffffffu, p0, 2);
            p1 += __shfl_xor_sync(0xffffffffu, p1, 1);
            p1 += __shfl_xor_sync(0xffffffffu, p1, 2);
            if (q == 0) {
                int r0 = wbase + g;
                if (r0 < N) {
                    unsigned long long key =
                        ((unsigned long long)fkey(p0) << 32) |
                        (unsigned long long)(~(unsigned int)r0);
                    if (key > wmax) wmax = key;
                    if (p0 > om) {
                        float cc = expf(om - p0);
                        ose = ose * cc + 1.f;
                        oss = oss * cc + p0;
                        om = p0;
                    } else {
                        float e = expf(p0 - om);
                        ose += e; oss += p0 * e;
                    }
                }
                int r1 = r0 + 8;
                if (r1 < N) {
                    unsigned long long key =
                        ((unsigned long long)fkey(p1) << 32) |
                        (unsigned long long)(~(unsigned int)r1);
                    if (key > wmax) wmax = key;
                    if (p1 > om) {
                        float cc = expf(om - p1);
                        ose = ose * cc + 1.f;
                        oss = oss * cc + p1;
                        om = p1;
                    } else {
                        float e = expf(p1 - om);
                        ose += e; oss += p1 * e;
                    }
                }
            }
        }
        __syncwarp();
    }

    // warp reduce
#pragma unroll
    for (int off = 16; off > 0; off >>= 1) {
        unsigned long long o = __shfl_xor_sync(0xffffffffu, wmax, off);
        if (o > wmax) wmax = o;
        float m2  = __shfl_xor_sync(0xffffffffu, om, off);
        float se2 = __shfl_xor_sync(0xffffffffu, ose, off);
        float ss2 = __shfl_xor_sync(0xffffffffu, oss, off);
        osm_merge(om, ose, oss, m2, se2, ss2);
    }
    if (lane == 0) { wkey[w] = wmax; wM[w] = om; wE[w] = ose; wS[w] = oss; }
    __syncthreads();
    if (t == 0) {
        unsigned long long k = wkey[0];
        float M2 = wM[0], E = wE[0], S = wS[0];
#pragma unroll
        for (int i = 1; i < MAIN_THREADS / 32; i++) {
            if (wkey[i] > k) k = wkey[i];
            osm_merge(M2, E, S, wM[i], wE[i], wS[i]);
        }
        atomicMax(&d_maxkey, k);
        d_blkM[blockIdx.x] = M2;
        d_blkE[blockIdx.x] = E;
        d_blkS[blockIdx.x] = S;
        __threadfence();
        unsigned prev = atomicAdd(&d_ticket, 1u);
        isLast = (prev == gridDim.x - 1u);
    }
    __syncthreads();

    // last block merges all block triples, writes outputs, resets counters
    if (isLast) {
        float Mm = -INFINITY; double E = 0.0, S = 0.0;
        for (int i = t; i < (int)gridDim.x; i += MAIN_THREADS) {
            float m2 = d_blkM[i];
            double e2 = d_blkE[i], s2 = d_blkS[i];
            float Mx = fmaxf(Mm, (e2 > 0.0) ? m2 : Mm);
            if (m2 > Mx && e2 > 0.0) Mx = m2;
            double a1 = (E > 0.0) ? exp((double)(Mm - Mx)) : 0.0;
            double a2 = (e2 > 0.0) ? exp((double)(m2 - Mx)) : 0.0;
            E = E * a1 + e2 * a2;
            S = S * a1 + s2 * a2;
            Mm = Mx;
        }
        fM[t] = Mm; fE[t] = E; fS[t] = S;
        __syncthreads();
        for (int o = MAIN_THREADS / 2; o > 0; o >>= 1) {
            if (t < o) {
                float m1 = fM[t], m2 = fM[t + o];
                double e1 = fE[t], e2 = fE[t + o];
                double s1 = fS[t], s2 = fS[t + o];
                float Mx = fmaxf((e1 > 0.0) ? m1 : -INFINITY,
                                 (e2 > 0.0) ? m2 : -INFINITY);
                double a1 = (e1 > 0.0) ? exp((double)(m1 - Mx)) : 0.0;
                double a2 = (e2 > 0.0) ? exp((double)(m2 - Mx)) : 0.0;
                fM[t] = Mx;
                fE[t] = e1 * a1 + e2 * a2;
                fS[t] = s1 * a1 + s2 * a2;
            }
            __syncthreads();
        }
        if (t == 0) {
            unsigned long long key = d_maxkey;
            unsigned int idx = ~(unsigned int)(key & 0xffffffffu);
            double sumexp = fE[0];
            double sums = fS[0];
            double lg = log(sumexp);
            out[0] = (float)idx;
            out[1] = (float)(1.0 / sumexp);
            out[2] = (float)(-lg);
            out[3] = (float)((double)fM[0] + lg - sums / sumexp);
            // reset counters for next graph replay (deterministic)
            d_maxkey = 0ull;
            d_tick_pre = 0u;
            d_ticket = 0u;
            __threadfence();
        }
    }
}

extern "C" void kernel_launch(void* const* d_in, const int* in_sizes, int n_in,
                              void* d_out, int out_size) {
    const float* x_graph = (const float*)d_in[0];
    const float* x_m     = (const float*)d_in[1];
    const float* x_job   = (const float*)d_in[2];
    const int*   m_ids   = (const int*)d_in[3];
    const int*   job_idx = (const int*)d_in[4];
    const float* W0      = (const float*)d_in[5];
    const float* b0      = (const float*)d_in[6];
    const float* W1      = (const float*)d_in[7];
    const float* b1      = (const float*)d_in[8];
    const float* W2      = (const float*)d_in[9];
    float* out = (float*)d_out;

    int M = in_sizes[1] / H;
    int J = in_sizes[2] / H;
    int N = in_sizes[3];
    if (M > MAXM) M = MAXM;
    if (J > MAXJ) J = MAXJ;

    const int smem_main =
        (8 * 32 * 36 + TILE * SAW + 16 * 4 * 4) * (int)sizeof(float);
    static int smem_set = 0;
    if (!smem_set) {
        cudaFuncSetAttribute(k_all, cudaFuncAttributeMaxDynamicSharedMemorySize,
                             smem_main);
        smem_set = 1;
    }
    k_all<<<MAIN_BLOCKS, MAIN_THREADS, smem_main>>>(
        x_graph, x_m, x_job, W0, b0, m_ids, job_idx, W1, b1, W2, M, J, N, out);
}